// round 15
// baseline (speedup 1.0000x reference)
#include <cuda_runtime.h>
#include <cstdint>

// LogicLayer: out[i,j] = g_a(x[i,idx_a[j]]) * g_b(x[i,idx_b[j]])
//   g(v) = (logit > 0) ? 1-v : v
//
// R15 vs R14 (52.9us = 48.5 main + 4.4us prep/launch gap):
//  - SINGLE kernel: on each thread's FIRST pair, it computes its own packed
//    gate words inline from idx/logits, gathers with them, and stores them
//    to g_packed (every CTA writes identical values; each thread re-reads
//    only its own writes on later pairs -> no cross-CTA sync needed).
//    Eliminates the prep kernel + its ~4us launch gap for ~1.5us of
//    amortized in-kernel packing.
//  - otherwise identical to R14: row-pair u16x2 fixed point in 128KB smem
//    (one LDS.32 feeds both rows; negation = XOR, exact), 2-deep packed
//    ring, persistent 148 CTAs, next-pair L2 prefetch, v4 .cs stores.
//    Quant rel_err ~1.1e-5 (threshold 1e-3).

#define IN_DIM   32768
#define OUT_DIM  32768
#define BATCH    1024
#define NPAIRS   (BATCH / 2)                  // 512
#define NTHREADS 1024
#define NSM      148
#define ITERS4   (OUT_DIM / (NTHREADS * 4))   // 8

__device__ __align__(16) uint32_t g_packed[OUT_DIM];

// ---------------- helpers ----------------------------------------------------
__device__ __forceinline__ void stg_cs_v4(float* p, float v0, float v1,
                                          float v2, float v3) {
    asm volatile("st.global.cs.v4.f32 [%0], {%1, %2, %3, %4};"
                 :: "l"(p), "f"(v0), "f"(v1), "f"(v2), "f"(v3) : "memory");
}

// one gate, both rows; branch-free negation masks from packed-word bits
__device__ __forceinline__ void gate_pair(uint32_t p, const uint32_t* spk,
                                          float& r0, float& r1) {
    uint32_t wa = spk[(p >> 16) & 0x7FFFu];
    uint32_t wb = spk[p & 0x7FFFu];
    wa ^= (uint32_t)((int32_t)p >> 31);            // bit31 -> 0 / 0xFFFFFFFF
    wb ^= (uint32_t)((int32_t)(p << 16) >> 31);    // bit15 -> 0 / 0xFFFFFFFF
    uint32_t lo = (wa & 0xFFFFu) * (wb & 0xFFFFu);
    uint32_t hi = (wa >> 16) * (wb >> 16);
    const float sc2 = 1.0f / (65535.0f * 65535.0f);
    r0 = __uint2float_rn(lo) * sc2;
    r1 = __uint2float_rn(hi) * sc2;
}

__device__ __forceinline__ uint32_t q16(float v) {
    return __float2uint_rn(v * 65535.0f);
}

__device__ __forceinline__ uint32_t pack_one(int ia, int ib, float la, float lb) {
    uint32_t fa = (la > 0.0f) ? 1u : 0u;
    uint32_t fb = (lb > 0.0f) ? 1u : 0u;
    return (fa << 31) | (((uint32_t)ia & 0x7FFFu) << 16)
         | (fb << 15) | ((uint32_t)ib & 0x7FFFu);
}

// ---------------- main: persistent, row-pair in smem as u32 ------------------
__global__ __launch_bounds__(NTHREADS, 1)
void logic_layer_kernel(const float* __restrict__ x,
                        const float* __restrict__ logits,
                        const int* __restrict__ idx_a,
                        const int* __restrict__ idx_b,
                        float* __restrict__ out) {
    extern __shared__ uint32_t spk[];          // 32768 x u32 = 128KB
    const int t = threadIdx.x;
    uint4* packed4 = reinterpret_cast<uint4*>(g_packed);

    bool first = true;

    for (int pr = blockIdx.x; pr < NPAIRS; pr += NSM) {
        const int row0 = 2 * pr;
        const int npr = pr + NSM;

        // Pull next pair (2 rows) toward L2 while we work.
        if (t == 0 && npr < NPAIRS) {
            asm volatile("cp.async.bulk.prefetch.L2.global [%0], %1;"
                         :: "l"(x + (size_t)(2 * npr) * IN_DIM),
                            "r"((uint32_t)(IN_DIM * 4)) : "memory");
        }
        if (t == 32 && npr < NPAIRS) {
            asm volatile("cp.async.bulk.prefetch.L2.global [%0], %1;"
                         :: "l"(x + (size_t)(2 * npr + 1) * IN_DIM),
                            "r"((uint32_t)(IN_DIM * 4)) : "memory");
        }

        // ---- conversion: both rows -> packed u16x2 in smem ----
        const float4* r0p = reinterpret_cast<const float4*>(x + (size_t)row0 * IN_DIM);
        const float4* r1p = reinterpret_cast<const float4*>(x + (size_t)(row0 + 1) * IN_DIM);
        #pragma unroll
        for (int k = 0; k < 8; k++) {
            int g = k * NTHREADS + t;
            float4 a = __ldcs(&r0p[g]);
            float4 b = __ldcs(&r1p[g]);
            uint4 w;
            w.x = q16(a.x) | (q16(b.x) << 16);
            w.y = q16(a.y) | (q16(b.y) << 16);
            w.z = q16(a.z) | (q16(b.z) << 16);
            w.w = q16(a.w) | (q16(b.w) << 16);
            reinterpret_cast<uint4*>(spk)[g] = w;
        }

        float* o0 = out + (size_t)row0 * OUT_DIM;
        float* o1 = o0 + OUT_DIM;

        if (first) {
            first = false;
            __syncthreads();
            // First pair: build packed words inline, use them, persist them.
            const int4*   ia4 = reinterpret_cast<const int4*>(idx_a);
            const int4*   ib4 = reinterpret_cast<const int4*>(idx_b);
            const float4* lg4 = reinterpret_cast<const float4*>(logits);
            #pragma unroll
            for (int k = 0; k < ITERS4; k++) {
                int g = k * NTHREADS + t;
                int4 ia = ia4[g];
                int4 ib = ib4[g];
                float4 l0 = lg4[2 * g];
                float4 l1 = lg4[2 * g + 1];
                uint4 p;
                p.x = pack_one(ia.x, ib.x, l0.x, l0.y);
                p.y = pack_one(ia.y, ib.y, l0.z, l0.w);
                p.z = pack_one(ia.z, ib.z, l1.x, l1.y);
                p.w = pack_one(ia.w, ib.w, l1.z, l1.w);
                packed4[g] = p;   // re-read only by this thread on later pairs

                float a0, a1, b0, b1, c0, c1, d0, d1;
                gate_pair(p.x, spk, a0, a1);
                gate_pair(p.y, spk, b0, b1);
                gate_pair(p.z, spk, c0, c1);
                gate_pair(p.w, spk, d0, d1);
                size_t off = (size_t)g * 4;
                stg_cs_v4(&o0[off], a0, b0, c0, d0);
                stg_cs_v4(&o1[off], a1, b1, c1, d1);
            }
        } else {
            // Prime the 2-deep packed ring BEFORE the barrier.
            uint4 pr0 = packed4[0 * NTHREADS + t];
            uint4 pr1 = packed4[1 * NTHREADS + t];
            __syncthreads();

            #pragma unroll
            for (int k = 0; k < ITERS4; k++) {
                uint4 p = (k & 1) ? pr1 : pr0;
                if (k + 2 < ITERS4) {
                    uint4 nx = packed4[(k + 2) * NTHREADS + t];
                    if (k & 1) pr1 = nx; else pr0 = nx;
                }
                float a0, a1, b0, b1, c0, c1, d0, d1;
                gate_pair(p.x, spk, a0, a1);
                gate_pair(p.y, spk, b0, b1);
                gate_pair(p.z, spk, c0, c1);
                gate_pair(p.w, spk, d0, d1);
                size_t off = (size_t)(k * NTHREADS + t) * 4;
                stg_cs_v4(&o0[off], a0, b0, c0, d0);
                stg_cs_v4(&o1[off], a1, b1, c1, d1);
            }
        }
        __syncthreads();   // smem free for next pair's conversion
    }
}

extern "C" void kernel_launch(void* const* d_in, const int* in_sizes, int n_in,
                              void* d_out, int out_size) {
    const float* x      = (const float*)d_in[0];
    const float* logits = (const float*)d_in[1];
    const int*   idx_a  = (const int*)d_in[2];
    const int*   idx_b  = (const int*)d_in[3];
    float* out = (float*)d_out;

    cudaFuncSetAttribute(logic_layer_kernel,
                         cudaFuncAttributeMaxDynamicSharedMemorySize,
                         IN_DIM * (int)sizeof(uint32_t));

    logic_layer_kernel<<<NSM, NTHREADS, IN_DIM * sizeof(uint32_t)>>>(
        x, logits, idx_a, idx_b, out);
}

// round 16
// speedup vs baseline: 1.0907x; 1.0907x over previous
#include <cuda_runtime.h>
#include <cstdint>

// LogicLayer: out[i,j] = g_a(x[i,idx_a[j]]) * g_b(x[i,idx_b[j]])
//   g(v) = (logit > 0) ? 1-v : v
//
// R16 = R14 base (best: 52.9us total / 48.5 main) + magic-number I2F:
//  - product converted to f32 via p16 = (ua*ub)>>16;
//    float(p16) == as_float(0x4B000000|p16) - 2^23 (exact), folded with the
//    fixed-point scale into ONE FFMA. Replaces the ~20-cyc XU CVT per row
//    with SHF+LOP3+FFMA (all 4-cyc fixed-lat) — shortens the per-gate
//    dependency chain ~2x in a latency-bound kernel.
//    Extra truncation err <= 65536/65535^2 ~ 1.5e-5 abs (threshold 1e-3).
//  - R15's inline packing reverted (register-pressure regression).

#define IN_DIM   32768
#define OUT_DIM  32768
#define BATCH    1024
#define NPAIRS   (BATCH / 2)                  // 512
#define NTHREADS 1024
#define NSM      148
#define ITERS4   (OUT_DIM / (NTHREADS * 4))   // 8

__device__ __align__(16) uint32_t g_packed[OUT_DIM];

// ---------------- prep: pack (fa|ia | fb|ib) into one u32 per j --------------
__global__ __launch_bounds__(256)
void prep_kernel(const float* __restrict__ logits,
                 const int* __restrict__ idx_a,
                 const int* __restrict__ idx_b) {
    int j = blockIdx.x * 256 + threadIdx.x;
    uint32_t ia = (uint32_t)idx_a[j] & 0x7FFFu;
    uint32_t ib = (uint32_t)idx_b[j] & 0x7FFFu;
    uint32_t fa = (logits[2 * j]     > 0.0f) ? 1u : 0u;
    uint32_t fb = (logits[2 * j + 1] > 0.0f) ? 1u : 0u;
    g_packed[j] = (fa << 31) | (ia << 16) | (fb << 15) | ib;
}

// ---------------- helpers ----------------------------------------------------
__device__ __forceinline__ void stg_cs_v4(float* p, float v0, float v1,
                                          float v2, float v3) {
    asm volatile("st.global.cs.v4.f32 [%0], {%1, %2, %3, %4};"
                 :: "l"(p), "f"(v0), "f"(v1), "f"(v2), "f"(v3) : "memory");
}

// one gate, both rows; branch-free negation; magic-number int->float
__device__ __forceinline__ void gate_pair(uint32_t p, const uint32_t* spk,
                                          float& r0, float& r1) {
    uint32_t wa = spk[(p >> 16) & 0x7FFFu];
    uint32_t wb = spk[p & 0x7FFFu];
    wa ^= (uint32_t)((int32_t)p >> 31);            // bit31 -> 0 / 0xFFFFFFFF
    wb ^= (uint32_t)((int32_t)(p << 16) >> 31);    // bit15 -> 0 / 0xFFFFFFFF
    uint32_t lo = (wa & 0xFFFFu) * (wb & 0xFFFFu);
    uint32_t hi = (wa >> 16) * (wb >> 16);
    // float(x>>16) = as_float(0x4B000000 | (x>>16)) - 2^23   (exact, x>>16 < 2^16)
    const float SC   = 65536.0f / (65535.0f * 65535.0f);  // scale for p16
    const float BIAS = -8388608.0f * (65536.0f / (65535.0f * 65535.0f));
    float f0 = __uint_as_float(0x4B000000u | (lo >> 16));
    float f1 = __uint_as_float(0x4B000000u | (hi >> 16));
    r0 = fmaf(f0, SC, BIAS);
    r1 = fmaf(f1, SC, BIAS);
}

__device__ __forceinline__ uint32_t q16(float v) {
    return __float2uint_rn(v * 65535.0f);
}

// ---------------- main: persistent, row-pair in smem as u32 ------------------
__global__ __launch_bounds__(NTHREADS, 1)
void logic_layer_kernel(const float* __restrict__ x,
                        float* __restrict__ out) {
    extern __shared__ uint32_t spk[];          // 32768 x u32 = 128KB
    const int t = threadIdx.x;
    const uint4* packed4 = reinterpret_cast<const uint4*>(g_packed);

    for (int pr = blockIdx.x; pr < NPAIRS; pr += NSM) {
        const int row0 = 2 * pr;
        const int npr = pr + NSM;

        // Pull next pair (2 rows) toward L2 while we work.
        if (t == 0 && npr < NPAIRS) {
            asm volatile("cp.async.bulk.prefetch.L2.global [%0], %1;"
                         :: "l"(x + (size_t)(2 * npr) * IN_DIM),
                            "r"((uint32_t)(IN_DIM * 4)) : "memory");
        }
        if (t == 32 && npr < NPAIRS) {
            asm volatile("cp.async.bulk.prefetch.L2.global [%0], %1;"
                         :: "l"(x + (size_t)(2 * npr + 1) * IN_DIM),
                            "r"((uint32_t)(IN_DIM * 4)) : "memory");
        }

        // ---- conversion: both rows -> packed u16x2 in smem ----
        const float4* r0p = reinterpret_cast<const float4*>(x + (size_t)row0 * IN_DIM);
        const float4* r1p = reinterpret_cast<const float4*>(x + (size_t)(row0 + 1) * IN_DIM);
        #pragma unroll
        for (int k = 0; k < 8; k++) {
            int g = k * NTHREADS + t;
            float4 a = __ldcs(&r0p[g]);
            float4 b = __ldcs(&r1p[g]);
            uint4 w;
            w.x = q16(a.x) | (q16(b.x) << 16);
            w.y = q16(a.y) | (q16(b.y) << 16);
            w.z = q16(a.z) | (q16(b.z) << 16);
            w.w = q16(a.w) | (q16(b.w) << 16);
            reinterpret_cast<uint4*>(spk)[g] = w;
        }

        // Prime the 2-deep packed ring BEFORE the barrier (loads fly over it).
        uint4 pr0 = packed4[0 * NTHREADS + t];
        uint4 pr1 = packed4[1 * NTHREADS + t];

        __syncthreads();

        // ---- gather phase: 4 gates x 2 rows per iteration, ring depth 2 ----
        float* o0 = out + (size_t)row0 * OUT_DIM;
        float* o1 = o0 + OUT_DIM;
        #pragma unroll
        for (int k = 0; k < ITERS4; k++) {
            uint4 p = (k & 1) ? pr1 : pr0;
            if (k + 2 < ITERS4) {
                uint4 nx = packed4[(k + 2) * NTHREADS + t];
                if (k & 1) pr1 = nx; else pr0 = nx;
            }
            float a0, a1, b0, b1, c0, c1, d0, d1;
            gate_pair(p.x, spk, a0, a1);
            gate_pair(p.y, spk, b0, b1);
            gate_pair(p.z, spk, c0, c1);
            gate_pair(p.w, spk, d0, d1);
            size_t off = (size_t)(k * NTHREADS + t) * 4;
            stg_cs_v4(&o0[off], a0, b0, c0, d0);
            stg_cs_v4(&o1[off], a1, b1, c1, d1);
        }
        __syncthreads();   // smem free for next pair's conversion
    }
}

extern "C" void kernel_launch(void* const* d_in, const int* in_sizes, int n_in,
                              void* d_out, int out_size) {
    const float* x      = (const float*)d_in[0];
    const float* logits = (const float*)d_in[1];
    const int*   idx_a  = (const int*)d_in[2];
    const int*   idx_b  = (const int*)d_in[3];
    float* out = (float*)d_out;

    cudaFuncSetAttribute(logic_layer_kernel,
                         cudaFuncAttributeMaxDynamicSharedMemorySize,
                         IN_DIM * (int)sizeof(uint32_t));

    prep_kernel<<<OUT_DIM / 256, 256>>>(logits, idx_a, idx_b);
    logic_layer_kernel<<<NSM, NTHREADS, IN_DIM * sizeof(uint32_t)>>>(x, out);
}

// round 17
// speedup vs baseline: 1.1182x; 1.0252x over previous
#include <cuda_runtime.h>
#include <cstdint>

// LogicLayer: out[i,j] = g_a(x[i,idx_a[j]]) * g_b(x[i,idx_b[j]])
//   g(v) = (logit > 0) ? 1-v : v
//
// R17 vs R16 (53.3us total / 49.5 main):
//  - LOAD BALANCE: 512 pairs / 148 CTAs left 80 CTAs idle for the last
//    quarter (makespan 4 pairs vs 3.46 avg). Now: pairs 0..443 whole
//    (exactly 3 per CTA); pairs 444..511 are split into 136 HALF-GATHER
//    tasks (CTA bid<136 converts pair 444+(bid>>1) fully but gathers only
//    j-half bid&1). Makespan 51.6k -> 46.7k wf (x0.905).
//  - gate math: R16 magic-number path kept (neutral), row-pair u16x2 smem,
//    2-deep packed ring per 4-iter range, L2 prefetch, v4 .cs stores.
//    Quant rel_err ~2.9e-5 (threshold 1e-3).

#define IN_DIM   32768
#define OUT_DIM  32768
#define BATCH    1024
#define NPAIRS   (BATCH / 2)                  // 512
#define NFULL    444                          // 148*3 whole pairs
#define NTHREADS 1024
#define NSM      148
#define ITERS4   (OUT_DIM / (NTHREADS * 4))   // 8

__device__ __align__(16) uint32_t g_packed[OUT_DIM];

// ---------------- prep: pack (fa|ia | fb|ib) into one u32 per j --------------
__global__ __launch_bounds__(256)
void prep_kernel(const float* __restrict__ logits,
                 const int* __restrict__ idx_a,
                 const int* __restrict__ idx_b) {
    int j = blockIdx.x * 256 + threadIdx.x;
    uint32_t ia = (uint32_t)idx_a[j] & 0x7FFFu;
    uint32_t ib = (uint32_t)idx_b[j] & 0x7FFFu;
    uint32_t fa = (logits[2 * j]     > 0.0f) ? 1u : 0u;
    uint32_t fb = (logits[2 * j + 1] > 0.0f) ? 1u : 0u;
    g_packed[j] = (fa << 31) | (ia << 16) | (fb << 15) | ib;
}

// ---------------- helpers ----------------------------------------------------
__device__ __forceinline__ void stg_cs_v4(float* p, float v0, float v1,
                                          float v2, float v3) {
    asm volatile("st.global.cs.v4.f32 [%0], {%1, %2, %3, %4};"
                 :: "l"(p), "f"(v0), "f"(v1), "f"(v2), "f"(v3) : "memory");
}

__device__ __forceinline__ void gate_pair(uint32_t p, const uint32_t* spk,
                                          float& r0, float& r1) {
    uint32_t wa = spk[(p >> 16) & 0x7FFFu];
    uint32_t wb = spk[p & 0x7FFFu];
    wa ^= (uint32_t)((int32_t)p >> 31);            // bit31 -> 0 / 0xFFFFFFFF
    wb ^= (uint32_t)((int32_t)(p << 16) >> 31);    // bit15 -> 0 / 0xFFFFFFFF
    uint32_t lo = (wa & 0xFFFFu) * (wb & 0xFFFFu);
    uint32_t hi = (wa >> 16) * (wb >> 16);
    const float SC   = 65536.0f / (65535.0f * 65535.0f);
    const float BIAS = -8388608.0f * (65536.0f / (65535.0f * 65535.0f));
    float f0 = __uint_as_float(0x4B000000u | (lo >> 16));
    float f1 = __uint_as_float(0x4B000000u | (hi >> 16));
    r0 = fmaf(f0, SC, BIAS);
    r1 = fmaf(f1, SC, BIAS);
}

__device__ __forceinline__ uint32_t q16(float v) {
    return __float2uint_rn(v * 65535.0f);
}

__device__ __forceinline__ void prefetch_pair(const float* x, int pr2) {
    asm volatile("cp.async.bulk.prefetch.L2.global [%0], %1;"
                 :: "l"(x + (size_t)pr2 * IN_DIM),
                    "r"((uint32_t)(IN_DIM * 4)) : "memory");
}

// convert rows (2*pr, 2*pr+1) into spk (u16x2 per element)
__device__ __forceinline__ void convert_pair(const float* __restrict__ x, int pr,
                                             uint32_t* spk, int t) {
    const float4* r0p = reinterpret_cast<const float4*>(x + (size_t)(2 * pr) * IN_DIM);
    const float4* r1p = reinterpret_cast<const float4*>(x + (size_t)(2 * pr + 1) * IN_DIM);
    #pragma unroll
    for (int k = 0; k < 8; k++) {
        int g = k * NTHREADS + t;
        float4 a = __ldcs(&r0p[g]);
        float4 b = __ldcs(&r1p[g]);
        uint4 w;
        w.x = q16(a.x) | (q16(b.x) << 16);
        w.y = q16(a.y) | (q16(b.y) << 16);
        w.z = q16(a.z) | (q16(b.z) << 16);
        w.w = q16(a.w) | (q16(b.w) << 16);
        reinterpret_cast<uint4*>(spk)[g] = w;
    }
}

// gather 4 k-iterations starting at kbeg; pr0/pr1 pre-primed for kbeg, kbeg+1
__device__ __forceinline__ void gather_range(int kbeg, uint4 pr0, uint4 pr1,
                                             const uint4* packed4,
                                             const uint32_t* spk,
                                             float* o0, float* o1, int t) {
    #pragma unroll
    for (int k = 0; k < 4; k++) {
        uint4 p = (k & 1) ? pr1 : pr0;
        if (k + 2 < 4) {
            uint4 nx = packed4[(kbeg + k + 2) * NTHREADS + t];
            if (k & 1) pr1 = nx; else pr0 = nx;
        }
        float a0, a1, b0, b1, c0, c1, d0, d1;
        gate_pair(p.x, spk, a0, a1);
        gate_pair(p.y, spk, b0, b1);
        gate_pair(p.z, spk, c0, c1);
        gate_pair(p.w, spk, d0, d1);
        size_t off = (size_t)((kbeg + k) * NTHREADS + t) * 4;
        stg_cs_v4(&o0[off], a0, b0, c0, d0);
        stg_cs_v4(&o1[off], a1, b1, c1, d1);
    }
}

// ---------------- main: persistent, balanced (3 full + <=1 half) -------------
__global__ __launch_bounds__(NTHREADS, 1)
void logic_layer_kernel(const float* __restrict__ x,
                        float* __restrict__ out) {
    extern __shared__ uint32_t spk[];          // 32768 x u32 = 128KB
    const int t = threadIdx.x;
    const int bid = blockIdx.x;
    const uint4* packed4 = reinterpret_cast<const uint4*>(g_packed);

    const bool has_half = (bid < 2 * (NPAIRS - NFULL));   // bid < 136
    const int  half_pr  = NFULL + (bid >> 1);
    const int  half_h   = bid & 1;

    #pragma unroll 1
    for (int i = 0; i < 3; i++) {
        const int pr = bid + i * NSM;          // < 444 always

        // Prefetch the NEXT task's rows while working on this one.
        if (t < 64 && (t & 31) == 0) {
            int npr = (i < 2) ? (pr + NSM) : (has_half ? half_pr : -1);
            if (npr >= 0) prefetch_pair(x, 2 * npr + (t >> 5));
        }

        convert_pair(x, pr, spk, t);

        // prime ring for first range before the barrier
        uint4 p0 = packed4[0 * NTHREADS + t];
        uint4 p1 = packed4[1 * NTHREADS + t];
        __syncthreads();

        float* o0 = out + (size_t)(2 * pr) * OUT_DIM;
        float* o1 = o0 + OUT_DIM;
        gather_range(0, p0, p1, packed4, spk, o0, o1, t);
        uint4 p4 = packed4[4 * NTHREADS + t];
        uint4 p5 = packed4[5 * NTHREADS + t];
        gather_range(4, p4, p5, packed4, spk, o0, o1, t);
        __syncthreads();                        // smem free for next conversion
    }

    if (has_half) {
        convert_pair(x, half_pr, spk, t);
        const int kbeg = half_h * 4;
        uint4 p0 = packed4[(kbeg + 0) * NTHREADS + t];
        uint4 p1 = packed4[(kbeg + 1) * NTHREADS + t];
        __syncthreads();
        float* o0 = out + (size_t)(2 * half_pr) * OUT_DIM;
        float* o1 = o0 + OUT_DIM;
        gather_range(kbeg, p0, p1, packed4, spk, o0, o1, t);
    }
}

extern "C" void kernel_launch(void* const* d_in, const int* in_sizes, int n_in,
                              void* d_out, int out_size) {
    const float* x      = (const float*)d_in[0];
    const float* logits = (const float*)d_in[1];
    const int*   idx_a  = (const int*)d_in[2];
    const int*   idx_b  = (const int*)d_in[3];
    float* out = (float*)d_out;

    cudaFuncSetAttribute(logic_layer_kernel,
                         cudaFuncAttributeMaxDynamicSharedMemorySize,
                         IN_DIM * (int)sizeof(uint32_t));

    prep_kernel<<<OUT_DIM / 256, 256>>>(logits, idx_a, idx_b);
    logic_layer_kernel<<<NSM, NTHREADS, IN_DIM * sizeof(uint32_t)>>>(x, out);
}